// round 11
// baseline (speedup 1.0000x reference)
#include <cuda_runtime.h>
#include <cstdint>
#include <math.h>

#define D 512
#define K 5
#define THREADS 256
#define BLOCKS 296    // persistent: 2 blocks/SM * 148
#define WPB (THREADS / 32)
#define STAGES 3
#define ROWB 2048     // bytes per staged row (512 floats)
#define SMEM_TOTAL (WPB * STAGES * ROWB + D * 4 + 32 * 4)

typedef unsigned long long ull;

__device__ __forceinline__ ull pack2(float lo, float hi) {
    ull r;
    asm("mov.b64 %0, {%1, %2};" : "=l"(r) : "f"(lo), "f"(hi));
    return r;
}
__device__ __forceinline__ void unpack2(ull v, float& lo, float& hi) {
    asm("mov.b64 {%0, %1}, %2;" : "=f"(lo), "=f"(hi) : "l"(v));
}
__device__ __forceinline__ ull fma2(ull a, ull b, ull c) {
    ull d;
    asm("fma.rn.f32x2 %0, %1, %2, %3;" : "=l"(d) : "l"(a), "l"(b), "l"(c));
    return d;
}
__device__ __forceinline__ ull mul2(ull a, ull b) {
    ull d;
    asm("mul.rn.f32x2 %0, %1, %2;" : "=l"(d) : "l"(a), "l"(b));
    return d;
}
__device__ __forceinline__ void cp16(uint32_t dst_smem, const void* src) {
    asm volatile("cp.async.ca.shared.global [%0], [%1], 16;"
                 :: "r"(dst_smem), "l"(src) : "memory");
}

// ---------------------------------------------------------------------------
// Fused kernel with per-warp cp.async ring (3 stages, depth-2 prefetch).
//   dist_k = x . w_k + pc2_k  (w = -2*alpha*c in regs; alpha*x^2 cancels)
//   rec_d  = rinv_d * sum_k mp_k * w_kd   (rinv = -0.5/alpha, shared)
//   pred   = sum_k mp_k * sigmoid(cw_k)
// In-flight x rows live in SMEM (not registers), so prefetch depth no longer
// fights the 80-reg weight slice for the register file.
// ---------------------------------------------------------------------------
__global__ __launch_bounds__(THREADS, 2) void lfr_fused(
    const float* __restrict__ x,          // (N, D)
    const float* __restrict__ alpha,      // (D,)
    const float* __restrict__ cw,         // (K,)
    const float* __restrict__ cent,       // (K, D)
    float* __restrict__ out_map,          // (N, K)
    float* __restrict__ out_rec,          // (N, D)
    float* __restrict__ out_pred,         // (N,)
    int n_rows)
{
    extern __shared__ __align__(16) char dynsmem[];
    char*  s_x    = dynsmem;                                  // [WPB][STAGES][ROWB]
    float* s_rinv = (float*)(dynsmem + WPB * STAGES * ROWB);  // -0.5/alpha
    float* s_swr  = s_rinv + D;                               // sigmoid(cw)

    const int tid  = threadIdx.x;
    const int lane = tid & 31;
    const int warp = tid >> 5;

    for (int i = tid; i < D; i += THREADS) s_rinv[i] = -0.5f / alpha[i];
    if (tid < K) s_swr[tid] = 1.0f / (1.0f + __expf(-cw[tid]));

    // ---- per-lane invariant setup: packed weights + c2 partials ----
    ull  w2[K][8];      // packed -2*alpha*c  (80 regs)
    float pc2[K];       // per-lane partial of sum(alpha*c^2)
    {
        float4 a4[4];
        #pragma unroll
        for (int j = 0; j < 4; j++)
            a4[j] = reinterpret_cast<const float4*>(alpha)[lane + j * 32];
        #pragma unroll
        for (int k = 0; k < K; k++) {
            pc2[k] = 0.0f;
            const float4* ck = reinterpret_cast<const float4*>(cent + k * D);
            #pragma unroll
            for (int j = 0; j < 4; j++) {
                const float4 c = ck[lane + j * 32];
                pc2[k] += a4[j].x * c.x * c.x + a4[j].y * c.y * c.y
                        + a4[j].z * c.z * c.z + a4[j].w * c.w * c.w;
                w2[k][2 * j]     = pack2(-2.0f * a4[j].x * c.x, -2.0f * a4[j].y * c.y);
                w2[k][2 * j + 1] = pack2(-2.0f * a4[j].z * c.z, -2.0f * a4[j].w * c.w);
            }
        }
    }
    __syncthreads();

    const int warp_global = (blockIdx.x * THREADS + tid) >> 5;
    const int nwarps      = (BLOCKS * THREADS) >> 5;

    // This warp's ring base (shared address space)
    const uint32_t ring = (uint32_t)__cvta_generic_to_shared(s_x)
                        + (uint32_t)(warp * STAGES * ROWB);
    char* ring_gen = s_x + warp * STAGES * ROWB;

    // ---- prime: stages 0,1 <- rows r, r+nwarps ----
    #pragma unroll
    for (int s = 0; s < STAGES - 1; s++) {
        const int r = warp_global + s * nwarps;
        if (r < n_rows) {
            const char* src = (const char*)(x + (size_t)r * D);
            const uint32_t dst = ring + s * ROWB;
            #pragma unroll
            for (int j = 0; j < 4; j++)
                cp16(dst + (lane + 32 * j) * 16, src + (lane + 32 * j) * 16);
        }
        asm volatile("cp.async.commit_group;" ::: "memory");
    }

    int row   = warp_global;
    int stage = 0;
    while (row < n_rows) {
        // Oldest group (this stage) complete; <=1 newer pending allowed
        asm volatile("cp.async.wait_group 1;" ::: "memory");

        // ---- read staged row: 4 x LDS.128, register pairs are f32x2 ----
        ull v2[8];
        const longlong2* sx =
            reinterpret_cast<const longlong2*>(ring_gen + stage * ROWB);
        #pragma unroll
        for (int j = 0; j < 4; j++) {
            const longlong2 ll = sx[lane + 32 * j];
            v2[2 * j] = (ull)ll.x; v2[2 * j + 1] = (ull)ll.y;
        }

        // ---- refill this ring slot's successor (depth-2) ----
        {
            const int pr = row + (STAGES - 1) * nwarps;
            if (pr < n_rows) {
                const char* src = (const char*)(x + (size_t)pr * D);
                const int ps = (stage + STAGES - 1) % STAGES;
                const uint32_t dst = ring + ps * ROWB;
                #pragma unroll
                for (int j = 0; j < 4; j++)
                    cp16(dst + (lane + 32 * j) * 16, src + (lane + 32 * j) * 16);
            }
            asm volatile("cp.async.commit_group;" ::: "memory");  // always (tail-safe)
        }

        // ---- distance fma stage: 40 FFMA2 ----
        ull acc[K];
        #pragma unroll
        for (int k = 0; k < K; k++) acc[k] = pack2(pc2[k], 0.0f);
        #pragma unroll
        for (int p = 0; p < 8; p++) {
            #pragma unroll
            for (int k = 0; k < K; k++)
                acc[k] = fma2(v2[p], w2[k][p], acc[k]);
        }

        // ---- warp butterfly reduce (5 independent chains) ----
        float dist[K];
        #pragma unroll
        for (int k = 0; k < K; k++) {
            float lo, hi;
            unpack2(acc[k], lo, hi);
            dist[k] = lo + hi;
        }
        #pragma unroll
        for (int k = 0; k < K; k++) {
            #pragma unroll
            for (int off = 16; off > 0; off >>= 1)
                dist[k] += __shfl_xor_sync(0xffffffffu, dist[k], off);
        }

        // ---- softmax over K=5 (replicated in all lanes) ----
        float m = dist[0];
        #pragma unroll
        for (int k = 1; k < K; k++) m = fmaxf(m, dist[k]);
        float mp[K];
        float s = 0.0f;
        #pragma unroll
        for (int k = 0; k < K; k++) { mp[k] = __expf(dist[k] - m); s += mp[k]; }
        const float inv = 1.0f / s;
        #pragma unroll
        for (int k = 0; k < K; k++) mp[k] *= inv;

        if (lane < K) out_map[(size_t)row * K + lane] = mp[lane];
        if (lane == 0) {
            float p = 0.0f;
            #pragma unroll
            for (int k = 0; k < K; k++) p += mp[k] * s_swr[k];
            out_pred[row] = p;
        }

        // ---- reconstruction: rec_d = rinv_d * sum_k mp_k * w_kd (packed) ----
        ull mp2[K];
        #pragma unroll
        for (int k = 0; k < K; k++) mp2[k] = pack2(mp[k], mp[k]);

        longlong2* orow = reinterpret_cast<longlong2*>(out_rec + (size_t)row * D);
        const longlong2* rinv2 = reinterpret_cast<const longlong2*>(s_rinv);
        #pragma unroll
        for (int j = 0; j < 4; j++) {
            ull sa = mul2(mp2[0], w2[0][2 * j]);
            ull sb = mul2(mp2[0], w2[0][2 * j + 1]);
            #pragma unroll
            for (int k = 1; k < K; k++) {
                sa = fma2(mp2[k], w2[k][2 * j], sa);
                sb = fma2(mp2[k], w2[k][2 * j + 1], sb);
            }
            const longlong2 rv = rinv2[lane + j * 32];   // LDS.128, conflict-free
            longlong2 o;
            o.x = (long long)mul2(sa, (ull)rv.x);
            o.y = (long long)mul2(sb, (ull)rv.y);
            orow[lane + j * 32] = o;                      // STG.128
        }

        row += nwarps;
        stage = (stage + 1) % STAGES;
    }
}

extern "C" void kernel_launch(void* const* d_in, const int* in_sizes, int n_in,
                              void* d_out, int out_size) {
    // metadata order: x, is_protected (unused), alpha_p, classif_w, centroids
    const float* x     = (const float*)d_in[0];
    const float* alpha = (const float*)d_in[2];
    const float* w     = (const float*)d_in[3];
    const float* cent  = (const float*)d_in[4];

    const int n_rows = in_sizes[0] / D;   // 65536

    float* out      = (float*)d_out;
    float* out_map  = out;                              // N*K
    float* out_rec  = out + (size_t)n_rows * K;         // N*D
    float* out_pred = out_rec + (size_t)n_rows * D;     // N

    static bool attr_set = false;
    if (!attr_set) {
        cudaFuncSetAttribute(lfr_fused,
                             cudaFuncAttributeMaxDynamicSharedMemorySize,
                             SMEM_TOTAL);
        attr_set = true;
    }
    lfr_fused<<<BLOCKS, THREADS, SMEM_TOTAL>>>(x, alpha, w, cent,
                                               out_map, out_rec, out_pred, n_rows);
}

// round 12
// speedup vs baseline: 1.0832x; 1.0832x over previous
#include <cuda_runtime.h>
#include <cstdint>
#include <math.h>

#define D 512
#define K 5
#define THREADS 256
#define BLOCKS 296    // persistent: 2 blocks/SM * 148

typedef unsigned long long ull;

__device__ __forceinline__ ull pack2(float lo, float hi) {
    ull r;
    asm("mov.b64 %0, {%1, %2};" : "=l"(r) : "f"(lo), "f"(hi));
    return r;
}
__device__ __forceinline__ void unpack2(ull v, float& lo, float& hi) {
    asm("mov.b64 {%0, %1}, %2;" : "=f"(lo), "=f"(hi) : "l"(v));
}
__device__ __forceinline__ ull fma2(ull a, ull b, ull c) {
    ull d;
    asm("fma.rn.f32x2 %0, %1, %2, %3;" : "=l"(d) : "l"(a), "l"(b), "l"(c));
    return d;
}
__device__ __forceinline__ ull mul2(ull a, ull b) {
    ull d;
    asm("mul.rn.f32x2 %0, %1, %2;" : "=l"(d) : "l"(a), "l"(b));
    return d;
}

// ---------------------------------------------------------------------------
// Fused kernel (R7 load scheme + packed reconstruction + streaming stores).
//   dist_k = x . w_k + pc2_k  (w = -2*alpha*c in regs; alpha*x^2 cancels in
//            softmax)                         -> butterfly -> softmax
//   rec_d  = rinv_d * sum_k mp_k * w_kd       (rinv = -0.5/alpha, shared)
//   pred   = sum_k mp_k * sigmoid(cw_k)
// x loaded as 8 x LDG.64 per lane (MLP=8); next row prefetched right after
// the fma stage so the reduce/softmax/rec tail hides the DRAM round-trip.
//   v2[p] = xr[2*lane + 64*(p>>1) + (p&1)]  pairs with  w2[k][p].
// ---------------------------------------------------------------------------
__global__ __launch_bounds__(THREADS, 2) void lfr_fused(
    const float* __restrict__ x,          // (N, D)
    const float* __restrict__ alpha,      // (D,)
    const float* __restrict__ cw,         // (K,)
    const float* __restrict__ cent,       // (K, D)
    float* __restrict__ out_map,          // (N, K)
    float* __restrict__ out_rec,          // (N, D)
    float* __restrict__ out_pred,         // (N,)
    int n_rows)
{
    __shared__ float s_rinv[D];           // -0.5 / alpha_d
    __shared__ float s_swr[K];            // sigmoid(cw_k)

    const int tid  = threadIdx.x;
    const int lane = tid & 31;

    for (int i = tid; i < D; i += THREADS) s_rinv[i] = -0.5f / alpha[i];
    if (tid < K) s_swr[tid] = 1.0f / (1.0f + __expf(-cw[tid]));

    // ---- per-lane invariant setup: packed weights + c2 partials ----
    ull  w2[K][8];      // packed -2*alpha*c  (80 regs)
    float pc2[K];       // per-lane partial of sum(alpha*c^2)
    {
        float4 a4[4];
        #pragma unroll
        for (int j = 0; j < 4; j++)
            a4[j] = reinterpret_cast<const float4*>(alpha)[lane + j * 32];
        #pragma unroll
        for (int k = 0; k < K; k++) {
            pc2[k] = 0.0f;
            const float4* ck = reinterpret_cast<const float4*>(cent + k * D);
            #pragma unroll
            for (int j = 0; j < 4; j++) {
                const float4 c = ck[lane + j * 32];
                pc2[k] += a4[j].x * c.x * c.x + a4[j].y * c.y * c.y
                        + a4[j].z * c.z * c.z + a4[j].w * c.w * c.w;
                w2[k][2 * j]     = pack2(-2.0f * a4[j].x * c.x, -2.0f * a4[j].y * c.y);
                w2[k][2 * j + 1] = pack2(-2.0f * a4[j].z * c.z, -2.0f * a4[j].w * c.w);
            }
        }
    }
    __syncthreads();

    const int warp_global = (blockIdx.x * THREADS + tid) >> 5;
    const int nwarps      = (BLOCKS * THREADS) >> 5;

    // Prime the pipeline: 8 x LDG.64 (max MLP)
    ull v2[8];
    int row = warp_global;
    if (row < n_rows) {
        const ull* xr = reinterpret_cast<const ull*>(x + (size_t)row * D);
        #pragma unroll
        for (int p = 0; p < 8; p++) v2[p] = xr[2 * lane + ((p >> 1) << 6) + (p & 1)];
    }

    while (row < n_rows) {
        // ---- distance fma stage: 40 FFMA2 ----
        ull acc[K];
        #pragma unroll
        for (int k = 0; k < K; k++) acc[k] = pack2(pc2[k], 0.0f);
        #pragma unroll
        for (int p = 0; p < 8; p++) {
            #pragma unroll
            for (int k = 0; k < K; k++)
                acc[k] = fma2(v2[p], w2[k][p], acc[k]);
        }

        // ---- prefetch next row: the whole tail below hides this latency ----
        const int nrow = row + nwarps;
        if (nrow < n_rows) {
            const ull* xr = reinterpret_cast<const ull*>(x + (size_t)nrow * D);
            #pragma unroll
            for (int p = 0; p < 8; p++) v2[p] = xr[2 * lane + ((p >> 1) << 6) + (p & 1)];
        }

        // ---- warp butterfly reduce (5 independent chains) ----
        float dist[K];
        #pragma unroll
        for (int k = 0; k < K; k++) {
            float lo, hi;
            unpack2(acc[k], lo, hi);
            dist[k] = lo + hi;
        }
        #pragma unroll
        for (int k = 0; k < K; k++) {
            #pragma unroll
            for (int off = 16; off > 0; off >>= 1)
                dist[k] += __shfl_xor_sync(0xffffffffu, dist[k], off);
        }

        // ---- softmax over K=5 (replicated in all lanes) ----
        float m = dist[0];
        #pragma unroll
        for (int k = 1; k < K; k++) m = fmaxf(m, dist[k]);
        float mp[K];
        float s = 0.0f;
        #pragma unroll
        for (int k = 0; k < K; k++) { mp[k] = __expf(dist[k] - m); s += mp[k]; }
        const float inv = 1.0f / s;
        #pragma unroll
        for (int k = 0; k < K; k++) mp[k] *= inv;

        if (lane < K) out_map[(size_t)row * K + lane] = mp[lane];
        if (lane == 0) {
            float p = 0.0f;
            #pragma unroll
            for (int k = 0; k < K; k++) p += mp[k] * s_swr[k];
            out_pred[row] = p;
        }

        // ---- reconstruction: rec_d = rinv_d * sum_k mp_k * w_kd (packed) ----
        ull mp2[K];
        #pragma unroll
        for (int k = 0; k < K; k++) mp2[k] = pack2(mp[k], mp[k]);

        ulonglong2* orow = reinterpret_cast<ulonglong2*>(out_rec + (size_t)row * D);
        const ulonglong2* rinv2 = reinterpret_cast<const ulonglong2*>(s_rinv);
        #pragma unroll
        for (int j = 0; j < 4; j++) {
            ull sa = mul2(mp2[0], w2[0][2 * j]);
            ull sb = mul2(mp2[0], w2[0][2 * j + 1]);
            #pragma unroll
            for (int k = 1; k < K; k++) {
                sa = fma2(mp2[k], w2[k][2 * j], sa);
                sb = fma2(mp2[k], w2[k][2 * j + 1], sb);
            }
            const ulonglong2 rv = rinv2[lane + j * 32];   // LDS.128, conflict-free
            ulonglong2 o;
            o.x = mul2(sa, rv.x);
            o.y = mul2(sb, rv.y);
            __stcs(orow + lane + j * 32, o);              // STG.128 streaming
        }

        row = nrow;
    }
}

extern "C" void kernel_launch(void* const* d_in, const int* in_sizes, int n_in,
                              void* d_out, int out_size) {
    // metadata order: x, is_protected (unused), alpha_p, classif_w, centroids
    const float* x     = (const float*)d_in[0];
    const float* alpha = (const float*)d_in[2];
    const float* w     = (const float*)d_in[3];
    const float* cent  = (const float*)d_in[4];

    const int n_rows = in_sizes[0] / D;   // 65536

    float* out      = (float*)d_out;
    float* out_map  = out;                              // N*K
    float* out_rec  = out + (size_t)n_rows * K;         // N*D
    float* out_pred = out_rec + (size_t)n_rows * D;     // N

    lfr_fused<<<BLOCKS, THREADS>>>(x, alpha, w, cent, out_map, out_rec, out_pred, n_rows);
}